// round 14
// baseline (speedup 1.0000x reference)
#include <cuda_runtime.h>
#include <cstdint>

#define NMAX  37       // max grid-point span per axis
#define CH    64
#define HH    200
#define WW    304
#define HW    (HH * WW)
#define SCALEF 0.0625f
#define NWARPS 4       // warps per block
#define CGRP  16       // channel groups (blocks per roi); CH/CGRP = 4 ch/block, 1 ch/warp

struct __align__(8) WI {
    float w;
    int   off;
};

__global__ __launch_bounds__(128) void prroi_kernel(
    const float* __restrict__ feats,
    const float* __restrict__ rois,
    float* __restrict__ out)
{
    __shared__ __align__(16) float s_wyd[NMAX * 8];   // dense y weights: [r][i], stride 8
    __shared__ WI    s_cy[49];                         // y taps: UNCLIPPED abs idx + weight
    __shared__ WI    s_cxr[49];                        // x taps: converted (w, xrel*7)
    __shared__ WI    s_cx[49];                         // x taps: UNCLIPPED abs idx + weight
    __shared__ float s_misc[8];                        // [6]=binszx [7]=binszy
    __shared__ __align__(16) float s_cold[NWARPS][260]; // per-warp coldot, 1 channel

    const int n   = blockIdx.x;
    const int g   = blockIdx.y;          // channel group
    const int tid = threadIdx.x;

    // zero dense y-weight table (all threads)
    for (int k = tid; k < NMAX * 8; k += 128) s_wyd[k] = 0.f;

    // ---- Phase 0: exact separable 1-D weights (replicates _axis_weights) ----
    if (tid < 14) {
        const int axis = (tid >= 7) ? 1 : 0;   // 0=x, 1=y
        const int p    = tid - axis * 7;
        const float lo = __ldg(&rois[n * 5 + 1 + axis]) * SCALEF;
        const float hi = __ldg(&rois[n * 5 + 3 + axis]) * SCALEF;
        const int size = axis ? HH : WW;
        const float length = fmaxf(hi - lo, 0.f);
        const float binsz  = length / 7.f;
        const float ws = lo + binsz * (float)p;
        const float we = ws + binsz;
        const float s  = floorf(ws);
        float Lk[6], Rk[6];
        #pragma unroll
        for (int k = 0; k < 6; k++) {
            const float cell = s + (float)k;
            const bool  act  = cell < we;
            const float x0 = fmaxf(ws, cell);
            const float x1 = fminf(we, cell + 1.f);
            const float a  = x0 - cell, la = x1 - cell;
            Lk[k] = act ? (la - 0.5f * la * la - a + 0.5f * a * a) : 0.f;
            const float a2 = cell + 1.f - x1, la2 = cell + 1.f - x0;
            Rk[k] = act ? (la2 - 0.5f * la2 * la2 - a2 + 0.5f * a2 * a2) : 0.f;
        }
        WI* dst = axis ? s_cy : s_cx;
        const int si = (int)s;
        #pragma unroll
        for (int t = 0; t < 7; t++) {
            float w = 0.f;
            if (t < 6) w += Lk[t];
            if (t > 0) w += Rk[t - 1];
            const int idx = si + t;                 // UNCLIPPED
            const bool valid = (idx >= 0) && (idx < size);
            dst[p * 7 + t].w   = valid ? w : 0.f;
            dst[p * 7 + t].off = idx;
        }
        if (p == 0) s_misc[6 + axis] = binsz;
    }
    __syncthreads();

    // ---- every thread derives bounds locally (read-only on taps) ----
    const int b = (int)__ldg(&rois[n * 5]);
    const int xlo = min(max(s_cx[0].off,  0), WW - 1);
    const int xhi = min(max(s_cx[48].off, 0), WW - 1);
    const int ylo = min(max(s_cy[0].off,  0), HH - 1);
    const int yhi = min(max(s_cy[48].off, 0), HH - 1);
    const int NX = xhi - xlo + 1;
    const int NR = yhi - ylo + 1;
    const float win = s_misc[6] * s_misc[7];
    const float coef = (win > 0.f) ? (1.f / fmaxf(win, 1e-12f)) : 0.f;

    // ---- convert x taps + scatter dense y weights (unique slots, no races) ----
    if (tid < 49) {
        const WI ex = s_cx[tid];
        WI o;
        o.w = ex.w;
        o.off = (min(max(ex.off, 0), WW - 1) - xlo) * 7;
        s_cxr[tid] = o;

        const WI ey = s_cy[tid];
        if (ey.off >= 0 && ey.off < HH) {
            // (i, row) unique across valid taps -> race-free add
            s_wyd[(ey.off - ylo) * 8 + tid / 7] += ey.w;
        }
    }
    __syncthreads();

    const int warp = tid >> 5, lane = tid & 31;
    float* sc = s_cold[warp];

    const float* base = feats + ((size_t)b * CH) * HW + (size_t)ylo * WW + xlo;

    // this block handles channels [g*4, g*4+4); warp handles channel g*4 + warp
    const int c0 = g * (CH / CGRP) + warp;
    const float* p0 = base + (size_t)c0 * HW;

    // ---- column-dot: cd[i] = sum_r WyD[r][i] * F[r, x] ----
    for (int xb = 0; xb < NX; xb += 32) {
        const int x = xb + lane;
        const bool act = x < NX;
        float ca[7];
        #pragma unroll
        for (int i = 0; i < 7; i++) ca[i] = 0.f;

        const float* q0 = p0 + x;

        int r = 0;
        // main: 8 rows per chunk, loads explicitly front-batched (MLP = 8)
        for (; r + 7 < NR; r += 8) {
            float v[8];
            #pragma unroll
            for (int u = 0; u < 8; u++)
                v[u] = act ? __ldg(q0 + (r + u) * WW) : 0.f;
            #pragma unroll
            for (int u = 0; u < 8; u++) {
                const float4 wA = *(const float4*)(s_wyd + (r + u) * 8);
                const float4 wB = *(const float4*)(s_wyd + (r + u) * 8 + 4);
                ca[0] = fmaf(wA.x, v[u], ca[0]);
                ca[1] = fmaf(wA.y, v[u], ca[1]);
                ca[2] = fmaf(wA.z, v[u], ca[2]);
                ca[3] = fmaf(wA.w, v[u], ca[3]);
                ca[4] = fmaf(wB.x, v[u], ca[4]);
                ca[5] = fmaf(wB.y, v[u], ca[5]);
                ca[6] = fmaf(wB.z, v[u], ca[6]);
            }
        }
        // remainder rows (front-batch 4 then scalar)
        for (; r + 3 < NR; r += 4) {
            float v[4];
            #pragma unroll
            for (int u = 0; u < 4; u++)
                v[u] = act ? __ldg(q0 + (r + u) * WW) : 0.f;
            #pragma unroll
            for (int u = 0; u < 4; u++) {
                const float4 wA = *(const float4*)(s_wyd + (r + u) * 8);
                const float4 wB = *(const float4*)(s_wyd + (r + u) * 8 + 4);
                ca[0] = fmaf(wA.x, v[u], ca[0]);
                ca[1] = fmaf(wA.y, v[u], ca[1]);
                ca[2] = fmaf(wA.z, v[u], ca[2]);
                ca[3] = fmaf(wA.w, v[u], ca[3]);
                ca[4] = fmaf(wB.x, v[u], ca[4]);
                ca[5] = fmaf(wB.y, v[u], ca[5]);
                ca[6] = fmaf(wB.z, v[u], ca[6]);
            }
        }
        for (; r < NR; r++) {
            const float v0 = act ? __ldg(q0 + r * WW) : 0.f;
            const float4 wA = *(const float4*)(s_wyd + r * 8);
            const float4 wB = *(const float4*)(s_wyd + r * 8 + 4);
            ca[0] = fmaf(wA.x, v0, ca[0]);
            ca[1] = fmaf(wA.y, v0, ca[1]);
            ca[2] = fmaf(wA.z, v0, ca[2]);
            ca[3] = fmaf(wA.w, v0, ca[3]);
            ca[4] = fmaf(wB.x, v0, ca[4]);
            ca[5] = fmaf(wB.y, v0, ca[5]);
            ca[6] = fmaf(wB.z, v0, ca[6]);
        }

        if (act) {
            #pragma unroll
            for (int i = 0; i < 7; i++)
                sc[x * 7 + i] = ca[i];
        }
    }
    __syncwarp();

    // ---- x-combine: out[i][j] = coef * sum_b Wx[j,b] * coldot[gxrel][i] ----
    float* o0 = out + ((size_t)n * CH + c0) * 49;
    #pragma unroll
    for (int half = 0; half < 2; half++) {
        const int it = lane + half * 32;
        if (it < 49) {
            const int i = it / 7;
            const int j = it - i * 7;
            float a0 = 0.f;
            #pragma unroll
            for (int bb = 0; bb < 7; bb++) {
                const WI e = s_cxr[j * 7 + bb];
                a0 = fmaf(e.w, sc[e.off + i], a0);
            }
            o0[it] = a0 * coef;
        }
    }
}

extern "C" void kernel_launch(void* const* d_in, const int* in_sizes, int n_in,
                              void* d_out, int out_size) {
    const float* feats = (const float*)d_in[0];
    const float* rois  = (const float*)d_in[1];
    float* out = (float*)d_out;
    const int N = in_sizes[1] / 5;
    prroi_kernel<<<dim3(N, CGRP), 128>>>(feats, rois, out);
}